// round 15
// baseline (speedup 1.0000x reference)
#include <cuda_runtime.h>
#include <math.h>
#include <stdint.h>

#define NN 2048
#define NE 32768
#define HD 128
#define CAP 128
#define HPAD 132

// ---------------- scratch (zero at module load; every call restores zeros) ----
__device__ int   g_adj[NN * NN];          // winning (edge+1) per (src,dst), 0 = none
__device__ int   g_wcnt_src[NN];          // winner (dedup'd) out-degree
__device__ int   g_cnt_dst[NN];           // in-degree
__device__ int   g_nb_col[NN * CAP];      // src bucket: dedup'd out-neighbor col
__device__ float g_nb_val[NN * CAP];      // src bucket: winner dist
__device__ int   g_in_edge[NN * CAP];     // dst bucket: incoming edge ids
__device__ float g_A[NN * HD];
__device__ float g_res[NE];
__device__ float g_wgt[NE];
__device__ float g_wm[NE * HD];           // unweighted messages
__device__ float g_agg[NN * HD];
__device__ float g_meanr[NN];

#define MMA_TF32(c, a0, a1, a2, a3, bb0, bb1)                              \
    asm volatile(                                                          \
        "mma.sync.aligned.m16n8k8.row.col.f32.tf32.tf32.f32 "              \
        "{%0,%1,%2,%3}, {%4,%5,%6,%7}, {%8,%9}, {%0,%1,%2,%3};"            \
        : "+f"((c)[0]), "+f"((c)[1]), "+f"((c)[2]), "+f"((c)[3])           \
        : "r"(a0), "r"(a1), "r"(a2), "r"(a3), "r"(bb0), "r"(bb1))

// 8-warp 64x128 tf32 GEMM over K=128 (warp covers 16 cols), acc c[4][2][4]
#define GEMM_K128(xu, W, c, n0, gid, tig)                                          \
    _Pragma("unroll 2")                                                            \
    for (int kt = 0; kt < 16; kt++) {                                              \
        int k0 = kt * 8;                                                           \
        uint32_t bf0[2], bf1[2];                                                   \
        _Pragma("unroll")                                                          \
        for (int nt = 0; nt < 2; nt++) {                                           \
            int n = (n0) + nt * 8 + (gid);                                         \
            bf0[nt] = __float_as_uint(__ldg(&(W)[(k0 + (tig)) * HD + n]));         \
            bf1[nt] = __float_as_uint(__ldg(&(W)[(k0 + (tig) + 4) * HD + n]));     \
        }                                                                          \
        uint32_t a0[4], a1[4], a2[4], a3[4];                                       \
        _Pragma("unroll")                                                          \
        for (int mt = 0; mt < 4; mt++) {                                           \
            int r0 = mt * 16 + (gid);                                              \
            a0[mt] = (xu)[r0 * HPAD + k0 + (tig)];                                 \
            a1[mt] = (xu)[(r0 + 8) * HPAD + k0 + (tig)];                           \
            a2[mt] = (xu)[r0 * HPAD + k0 + (tig) + 4];                             \
            a3[mt] = (xu)[(r0 + 8) * HPAD + k0 + (tig) + 4];                       \
        }                                                                          \
        _Pragma("unroll")                                                          \
        for (int mt = 0; mt < 4; mt++)                                             \
            _Pragma("unroll")                                                      \
            for (int nt = 0; nt < 2; nt++)                                         \
                MMA_TF32(c[mt][nt], a0[mt], a1[mt], a2[mt], a3[mt], bf0[nt], bf1[nt]);\
    }

#define ZERO_C2(c)                                                         \
    _Pragma("unroll")                                                      \
    for (int mt = 0; mt < 4; mt++)                                         \
        _Pragma("unroll")                                                  \
        for (int nt = 0; nt < 2; nt++)                                     \
            _Pragma("unroll")                                              \
            for (int q = 0; q < 4; q++) c[mt][nt][q] = 0.0f;

// ================= L1: edge scatter (blocks 0-127) || nodeA GEMM (blocks 128-159) =================
__global__ void __launch_bounds__(256) k_p1(const int* __restrict__ ei,
                                            const float* __restrict__ mu,
                                            const float* __restrict__ sigma,
                                            const float* __restrict__ w1,
                                            const float* __restrict__ b1) {
    __shared__ float xs[64 * HPAD];
    int b = blockIdx.x;
    int t = threadIdx.x;

    if (b < 128) {
        int e = b * 256 + t;
        int s = ei[e], d = ei[NE + e];
        atomicMax(&g_adj[s * NN + d], e + 1);
        int q = atomicAdd(&g_cnt_dst[d], 1);
        g_in_edge[d * CAP + q] = e;
        return;
    }

    // nodeA: g_A = [mu,sigma] @ W1[0:256] + b1  (64-node tile)
    int nb = (b - 128) * 64;
    int tt = t & 127, hh = t >> 7;
    int warp = t >> 5, lane = t & 31, gid = lane >> 2, tig = lane & 3;
    int n0 = warp * 16;
    const uint32_t* xu = (const uint32_t*)xs;

    float c[4][2][4];
    ZERO_C2(c);
    #pragma unroll 1
    for (int half = 0; half < 2; half++) {
        const float* src = half ? sigma : mu;
        __syncthreads();
        for (int x = hh * 32; x < hh * 32 + 32; x++)
            xs[x * HPAD + tt] = src[(nb + x) * HD + tt];
        __syncthreads();
        const float* W = w1 + half * 128 * HD;
        GEMM_K128(xu, W, c, n0, gid, tig);
    }
    #pragma unroll
    for (int nt = 0; nt < 2; nt++) {
        int n = n0 + nt * 8 + 2 * tig;
        float bb0 = __ldg(&b1[n]);
        float bb1 = __ldg(&b1[n + 1]);
        #pragma unroll
        for (int mt = 0; mt < 4; mt++) {
            int m0 = nb + mt * 16 + gid;
            int m1 = m0 + 8;
            *(float2*)&g_A[m0 * HD + n] = make_float2(c[mt][nt][0] + bb0, c[mt][nt][1] + bb1);
            *(float2*)&g_A[m1 * HD + n] = make_float2(c[mt][nt][2] + bb0, c[mt][nt][3] + bb1);
        }
    }
}

// ================= L2: winner fill (blocks 0-127) || edge GEMM (blocks 128-639) =================
__global__ void __launch_bounds__(256) k_p2(const int* __restrict__ ei,
                                            const float* __restrict__ dist,
                                            const float* __restrict__ conf,
                                            const float* __restrict__ ang,
                                            const float* __restrict__ dep,
                                            const float* __restrict__ w1,
                                            const float* __restrict__ w2,
                                            const float* __restrict__ b2) {
    __shared__ float xs[64 * HPAD];
    int b = blockIdx.x;
    int t = threadIdx.x;

    if (b < 128) {
        int e = b * 256 + t;
        int s = ei[e], d = ei[NE + e];
        if (g_adj[s * NN + d] == e + 1) {
            int p = atomicAdd(&g_wcnt_src[s], 1);
            g_nb_col[s * CAP + p] = d;
            g_nb_val[s * CAP + p] = dist[e];
        }
        return;
    }

    // edge GEMM: hid = relu(g_A[src] + feat@W1_feat); wm = hid @ W2 + b2 (unweighted)
    int eb = (b - 128) * 64;
    int tt = t & 127, hh = t >> 7;
    int warp = t >> 5, lane = t & 31, gid = lane >> 2, tig = lane & 3;
    int n0 = warp * 16;
    const uint32_t* xu = (const uint32_t*)xs;

    {
        float wf0 = w1[(256) * HD + tt];
        float wf1 = w1[(257) * HD + tt];
        float wf2 = w1[(258) * HD + tt];
        float wf3 = w1[(259) * HD + tt];
        #pragma unroll 4
        for (int x = hh * 32; x < hh * 32 + 32; x++) {
            int e = eb + x;
            int s = ei[e];
            float v = g_A[s * HD + tt]
                    + dist[e] * wf0 + conf[e] * wf1 + ang[e] * wf2 + dep[e] * wf3;
            xs[x * HPAD + tt] = fmaxf(v, 0.0f);
        }
    }
    __syncthreads();

    float c[4][2][4];
    ZERO_C2(c);
    GEMM_K128(xu, w2, c, n0, gid, tig);

    #pragma unroll
    for (int nt = 0; nt < 2; nt++) {
        int n = n0 + nt * 8 + 2 * tig;
        float bb0 = __ldg(&b2[n]);
        float bb1 = __ldg(&b2[n + 1]);
        #pragma unroll
        for (int mt = 0; mt < 4; mt++) {
            int e0 = eb + mt * 16 + gid;
            int e1 = e0 + 8;
            *(float2*)&g_wm[e0 * HD + n] = make_float2(c[mt][nt][0] + bb0, c[mt][nt][1] + bb1);
            *(float2*)&g_wm[e1 * HD + n] = make_float2(c[mt][nt][2] + bb0, c[mt][nt][3] + bb1);
        }
    }
}

// ================= L3: residuals, 16 lanes per edge (16 edges/block) =================
__global__ void __launch_bounds__(256) k_res(const int* __restrict__ ei,
                                             const float* __restrict__ dist,
                                             float* __restrict__ out_res) {
    int lane = threadIdx.x & 31;
    int l = lane & 15;
    int e = blockIdx.x * 16 + (threadIdx.x >> 5) * 2 + (lane >> 4);
    int s = ei[e], d = ei[NE + e];
    int nw = g_wcnt_src[s];
    int base = s * CAP;
    float sum = 0.0f; int cnt = 0;
    for (int i = l; i < nw; i += 16) {
        int B   = g_nb_col[base + i];
        float dab = g_nb_val[base + i];
        int idx = g_adj[B * NN + d];
        if (idx > 0) { sum += dab + dist[idx - 1]; cnt++; }
    }
    #pragma unroll
    for (int o = 8; o > 0; o >>= 1) {
        sum += __shfl_down_sync(0xffffffffu, sum, o, 16);
        cnt += __shfl_down_sync(0xffffffffu, cnt, o, 16);
    }
    if (l == 0) {
        float dac = dist[e];
        float mean = (cnt > 0) ? (sum / (float)cnt) : dac;
        float r = fabsf(dac - mean);
        g_res[e] = r;
        g_wgt[e] = expf(-r);
        out_res[e] = r;
    }
}

// ================= L4: aggregation (weighting here) + adj/src-count cleanup =================
__global__ void __launch_bounds__(128) k_agg(const int* __restrict__ ei) {
    int n = blockIdx.x;
    int t = threadIdx.x;

    int cnt = g_cnt_dst[n];

    if (t < 16) {
        int e = n * 16 + t;
        int s = ei[e], d = ei[NE + e];
        g_adj[s * NN + d] = 0;
    }
    if (n < 16) g_wcnt_src[n * 128 + t] = 0;

    int base = n * CAP;
    float acc = 0.0f, ws = 0.0f, rs = 0.0f;
    int i = 0;
    for (; i + 4 <= cnt; i += 4) {
        int e0 = g_in_edge[base + i];
        int e1 = g_in_edge[base + i + 1];
        int e2 = g_in_edge[base + i + 2];
        int e3 = g_in_edge[base + i + 3];
        float w0 = g_wgt[e0], w1 = g_wgt[e1], w2 = g_wgt[e2], w3 = g_wgt[e3];
        float m0 = __ldg(&g_wm[e0 * HD + t]);
        float m1 = __ldg(&g_wm[e1 * HD + t]);
        float m2 = __ldg(&g_wm[e2 * HD + t]);
        float m3 = __ldg(&g_wm[e3 * HD + t]);
        acc += m0 * w0 + m1 * w1 + m2 * w2 + m3 * w3;
        ws  += (w0 + w1) + (w2 + w3);
        rs  += (g_res[e0] + g_res[e1]) + (g_res[e2] + g_res[e3]);
    }
    for (; i < cnt; i++) {
        int e = g_in_edge[base + i];
        float w = g_wgt[e];
        acc += __ldg(&g_wm[e * HD + t]) * w;
        ws  += w;
        rs  += g_res[e];
    }
    g_agg[n * HD + t] = acc / fmaxf(ws, 1e-8f);
    if (t == 0) g_meanr[n] = rs / fmaxf((float)cnt, 1.0f);
}

// ================= L5: node MLPs via tf32 mma (64 blocks: 32 tiles x {mu,sigma}) =================
__global__ void __launch_bounds__(128) k_node(const float* __restrict__ mu,
                                              const float* __restrict__ muw1, const float* __restrict__ mub1,
                                              const float* __restrict__ muw2, const float* __restrict__ mub2,
                                              const float* __restrict__ sgw1, const float* __restrict__ sgb1,
                                              const float* __restrict__ sgw2, const float* __restrict__ sgb2,
                                              float* __restrict__ out) {
    __shared__ float xs[64 * HPAD];
    __shared__ float mr[64];
    int b = blockIdx.x;
    int path = b & 1;
    int nb = (b >> 1) * 64;
    int t = threadIdx.x;

    if (b < 16) g_cnt_dst[b * 128 + t] = 0;   // safe: k_agg (reader) finished

    for (int x = 0; x < 64; x++) xs[x * HPAD + t] = g_agg[(nb + x) * HD + t];
    if (t < 64) mr[t] = g_meanr[nb + t];
    __syncthreads();

    const float* W1 = path ? sgw1 : muw1;
    const float* B1 = path ? sgb1 : mub1;
    const float* W2 = path ? sgw2 : muw2;
    const float* B2 = path ? sgb2 : mub2;

    int warp = t >> 5, lane = t & 31, gid = lane >> 2, tig = lane & 3;
    int n0 = warp * 32;
    const uint32_t* xu = (const uint32_t*)xs;

    float c[4][4][4];

    #pragma unroll
    for (int mt = 0; mt < 4; mt++)
        #pragma unroll
        for (int nt = 0; nt < 4; nt++)
            #pragma unroll
            for (int q = 0; q < 4; q++) c[mt][nt][q] = 0.0f;

    #pragma unroll 2
    for (int kt = 0; kt < 16; kt++) {
        int k0 = kt * 8;
        uint32_t b0[4], b1[4];
        #pragma unroll
        for (int nt = 0; nt < 4; nt++) {
            int n = n0 + nt * 8 + gid;
            b0[nt] = __float_as_uint(__ldg(&W1[(k0 + tig) * HD + n]));
            b1[nt] = __float_as_uint(__ldg(&W1[(k0 + tig + 4) * HD + n]));
        }
        uint32_t a0[4], a1[4], a2[4], a3[4];
        #pragma unroll
        for (int mt = 0; mt < 4; mt++) {
            int r0 = mt * 16 + gid;
            a0[mt] = xu[r0 * HPAD + k0 + tig];
            a1[mt] = xu[(r0 + 8) * HPAD + k0 + tig];
            a2[mt] = xu[r0 * HPAD + k0 + tig + 4];
            a3[mt] = xu[(r0 + 8) * HPAD + k0 + tig + 4];
        }
        #pragma unroll
        for (int mt = 0; mt < 4; mt++)
            #pragma unroll
            for (int nt = 0; nt < 4; nt++)
                MMA_TF32(c[mt][nt], a0[mt], a1[mt], a2[mt], a3[mt], b0[nt], b1[nt]);
    }
    __syncthreads();

    #pragma unroll
    for (int nt = 0; nt < 4; nt++) {
        int n = n0 + nt * 8 + 2 * tig;
        float bb0 = __ldg(&B1[n]);
        float bb1 = __ldg(&B1[n + 1]);
        float wl0 = 0.0f, wl1 = 0.0f;
        if (path) { wl0 = __ldg(&sgw1[128 * HD + n]); wl1 = __ldg(&sgw1[128 * HD + n + 1]); }
        #pragma unroll
        for (int mt = 0; mt < 4; mt++) {
            int m0 = mt * 16 + gid;
            int m1 = m0 + 8;
            float e0 = path ? mr[m0] : 0.0f;
            float e1 = path ? mr[m1] : 0.0f;
            xs[m0 * HPAD + n]     = fmaxf(c[mt][nt][0] + bb0 + e0 * wl0, 0.0f);
            xs[m0 * HPAD + n + 1] = fmaxf(c[mt][nt][1] + bb1 + e0 * wl1, 0.0f);
            xs[m1 * HPAD + n]     = fmaxf(c[mt][nt][2] + bb0 + e1 * wl0, 0.0f);
            xs[m1 * HPAD + n + 1] = fmaxf(c[mt][nt][3] + bb1 + e1 * wl1, 0.0f);
        }
    }
    __syncthreads();

    #pragma unroll
    for (int mt = 0; mt < 4; mt++)
        #pragma unroll
        for (int nt = 0; nt < 4; nt++)
            #pragma unroll
            for (int q = 0; q < 4; q++) c[mt][nt][q] = 0.0f;

    #pragma unroll 2
    for (int kt = 0; kt < 16; kt++) {
        int k0 = kt * 8;
        uint32_t b0[4], b1[4];
        #pragma unroll
        for (int nt = 0; nt < 4; nt++) {
            int n = n0 + nt * 8 + gid;
            b0[nt] = __float_as_uint(__ldg(&W2[(k0 + tig) * HD + n]));
            b1[nt] = __float_as_uint(__ldg(&W2[(k0 + tig + 4) * HD + n]));
        }
        uint32_t a0[4], a1[4], a2[4], a3[4];
        #pragma unroll
        for (int mt = 0; mt < 4; mt++) {
            int r0 = mt * 16 + gid;
            a0[mt] = xu[r0 * HPAD + k0 + tig];
            a1[mt] = xu[(r0 + 8) * HPAD + k0 + tig];
            a2[mt] = xu[r0 * HPAD + k0 + tig + 4];
            a3[mt] = xu[(r0 + 8) * HPAD + k0 + tig + 4];
        }
        #pragma unroll
        for (int mt = 0; mt < 4; mt++)
            #pragma unroll
            for (int nt = 0; nt < 4; nt++)
                MMA_TF32(c[mt][nt], a0[mt], a1[mt], a2[mt], a3[mt], b0[nt], b1[nt]);
    }

    #pragma unroll
    for (int nt = 0; nt < 4; nt++) {
        int n = n0 + nt * 8 + 2 * tig;
        float bb0 = __ldg(&B2[n]);
        float bb1 = __ldg(&B2[n + 1]);
        #pragma unroll
        for (int mt = 0; mt < 4; mt++) {
            int m0 = nb + mt * 16 + gid;
            int m1 = m0 + 8;
            float v00 = c[mt][nt][0] + bb0, v01 = c[mt][nt][1] + bb1;
            float v10 = c[mt][nt][2] + bb0, v11 = c[mt][nt][3] + bb1;
            if (!path) {
                float2 mu0 = *(const float2*)&mu[m0 * HD + n];
                float2 mu1 = *(const float2*)&mu[m1 * HD + n];
                *(float2*)&out[m0 * HD + n] = make_float2(mu0.x + v00, mu0.y + v01);
                *(float2*)&out[m1 * HD + n] = make_float2(mu1.x + v10, mu1.y + v11);
            } else {
                float s00 = fmaxf(v00, 0.0f) + log1pf(expf(-fabsf(v00)));
                float s01 = fmaxf(v01, 0.0f) + log1pf(expf(-fabsf(v01)));
                float s10 = fmaxf(v10, 0.0f) + log1pf(expf(-fabsf(v10)));
                float s11 = fmaxf(v11, 0.0f) + log1pf(expf(-fabsf(v11)));
                *(float2*)&out[NN * HD + m0 * HD + n] = make_float2(s00, s01);
                *(float2*)&out[NN * HD + m1 * HD + n] = make_float2(s10, s11);
            }
        }
    }
}

// ---------------- launch: 5 plain nodes, no streams ----------------
extern "C" void kernel_launch(void* const* d_in, const int* in_sizes, int n_in,
                              void* d_out, int out_size) {
    const float* mu    = (const float*)d_in[0];
    const float* sigma = (const float*)d_in[1];
    const int*   ei    = (const int*)d_in[2];
    const float* dist  = (const float*)d_in[3];
    const float* conf  = (const float*)d_in[4];
    const float* ang   = (const float*)d_in[5];
    const float* dep   = (const float*)d_in[6];
    const float* msgw1 = (const float*)d_in[7];
    const float* msgb1 = (const float*)d_in[8];
    const float* msgw2 = (const float*)d_in[9];
    const float* msgb2 = (const float*)d_in[10];
    const float* muw1  = (const float*)d_in[11];
    const float* mub1  = (const float*)d_in[12];
    const float* muw2  = (const float*)d_in[13];
    const float* mub2  = (const float*)d_in[14];
    const float* sgw1  = (const float*)d_in[15];
    const float* sgb1  = (const float*)d_in[16];
    const float* sgw2  = (const float*)d_in[17];
    const float* sgb2  = (const float*)d_in[18];
    float* out = (float*)d_out;
    float* out_res = out + 2 * NN * HD;

    k_p1<<<128 + 32, 256>>>(ei, mu, sigma, msgw1, msgb1);
    k_p2<<<128 + 512, 256>>>(ei, dist, conf, ang, dep, msgw1, msgw2, msgb2);
    k_res<<<NE / 16, 256>>>(ei, dist, out_res);
    k_agg<<<NN, 128>>>(ei);
    k_node<<<2 * (NN / 64), 128>>>(mu, muw1, mub1, muw2, mub2, sgw1, sgb1, sgw2, sgb2, out);
}

// round 16
// speedup vs baseline: 1.0615x; 1.0615x over previous
#include <cuda_runtime.h>
#include <cuda_bf16.h>
#include <math.h>
#include <stdint.h>

#define NN 2048
#define NE 32768
#define HD 128
#define CAP 128
#define HPAD 132

// ---------------- scratch (zero at module load; every call restores zeros) ----
__device__ int      g_adj[NN * NN];       // winning (edge+1) per (src,dst), 0 = none
__device__ int      g_wcnt_src[NN];
__device__ int      g_cnt_dst[NN];
__device__ int      g_nb_col[NN * CAP];
__device__ float    g_nb_val[NN * CAP];
__device__ int      g_in_edge[NN * CAP];
__device__ float    g_A[NN * HD];
__device__ float    g_res[NE];
__device__ float    g_wgt[NE];
__device__ uint32_t g_wmh[NE * (HD / 2)]; // messages as bf16x2 (8.4 MB)
__device__ float    g_agg[NN * HD];
__device__ float    g_meanr[NN];

#define MMA_TF32(c, a0, a1, a2, a3, bb0, bb1)                              \
    asm volatile(                                                          \
        "mma.sync.aligned.m16n8k8.row.col.f32.tf32.tf32.f32 "              \
        "{%0,%1,%2,%3}, {%4,%5,%6,%7}, {%8,%9}, {%0,%1,%2,%3};"            \
        : "+f"((c)[0]), "+f"((c)[1]), "+f"((c)[2]), "+f"((c)[3])           \
        : "r"(a0), "r"(a1), "r"(a2), "r"(a3), "r"(bb0), "r"(bb1))

// ---------------- chain A1: adj scatter + dst bucket ----------------
__global__ void k_scatcnt(const int* __restrict__ ei) {
    int e = blockIdx.x * blockDim.x + threadIdx.x;
    if (e >= NE) return;
    int s = ei[e], d = ei[NE + e];
    atomicMax(&g_adj[s * NN + d], e + 1);
    int q = atomicAdd(&g_cnt_dst[d], 1);
    g_in_edge[d * CAP + q] = e;
}

// ---------------- chain A2: src winner bucket (dedup'd) ----------------
__global__ void k_fill(const int* __restrict__ ei, const float* __restrict__ dist) {
    int e = blockIdx.x * blockDim.x + threadIdx.x;
    if (e >= NE) return;
    int s = ei[e], d = ei[NE + e];
    if (g_adj[s * NN + d] == e + 1) {
        int p = atomicAdd(&g_wcnt_src[s], 1);
        g_nb_col[s * CAP + p] = d;
        g_nb_val[s * CAP + p] = dist[e];
    }
}

// ---------------- chain A3: residuals, 16 lanes per edge ----------------
__global__ void __launch_bounds__(256) k_res(const int* __restrict__ ei,
                                             const float* __restrict__ dist,
                                             float* __restrict__ out_res) {
    int lane = threadIdx.x & 31;
    int l = lane & 15;
    int e = blockIdx.x * 16 + (threadIdx.x >> 5) * 2 + (lane >> 4);
    int s = ei[e], d = ei[NE + e];
    int nw = g_wcnt_src[s];
    int base = s * CAP;
    float sum = 0.0f; int cnt = 0;
    for (int i = l; i < nw; i += 16) {
        int B   = g_nb_col[base + i];
        float dab = g_nb_val[base + i];
        int idx = g_adj[B * NN + d];
        if (idx > 0) { sum += dab + dist[idx - 1]; cnt++; }
    }
    #pragma unroll
    for (int o = 8; o > 0; o >>= 1) {
        sum += __shfl_down_sync(0xffffffffu, sum, o, 16);
        cnt += __shfl_down_sync(0xffffffffu, cnt, o, 16);
    }
    if (l == 0) {
        float dac = dist[e];
        float mean = (cnt > 0) ? (sum / (float)cnt) : dac;
        float r = fabsf(dac - mean);
        g_res[e] = r;
        g_wgt[e] = expf(-r);
        out_res[e] = r;
    }
}

// ---------------- chain B1 (side stream): nodeA via tf32 mma ----------------
__global__ void __launch_bounds__(128) k_nodeA(const float* __restrict__ mu,
                                               const float* __restrict__ sig,
                                               const float* __restrict__ w1,
                                               const float* __restrict__ b1) {
    __shared__ float xs[64 * HPAD];
    int t = threadIdx.x;
    int nb = blockIdx.x * 64;
    int warp = t >> 5, lane = t & 31, gid = lane >> 2, tig = lane & 3;
    int n0 = warp * 32;
    const uint32_t* xu = (const uint32_t*)xs;

    float c[4][4][4];
    #pragma unroll
    for (int mt = 0; mt < 4; mt++)
        #pragma unroll
        for (int nt = 0; nt < 4; nt++)
            #pragma unroll
            for (int q = 0; q < 4; q++) c[mt][nt][q] = 0.0f;

    #pragma unroll 1
    for (int half = 0; half < 2; half++) {
        const float* src = half ? sig : mu;
        __syncthreads();
        for (int x = 0; x < 64; x++) xs[x * HPAD + t] = src[(nb + x) * HD + t];
        __syncthreads();
        int koff = half * 128;
        #pragma unroll 2
        for (int kt = 0; kt < 16; kt++) {
            int k0 = kt * 8;
            uint32_t b0[4], b1f[4];
            #pragma unroll
            for (int nt = 0; nt < 4; nt++) {
                int n = n0 + nt * 8 + gid;
                b0[nt]  = __float_as_uint(__ldg(&w1[(koff + k0 + tig) * HD + n]));
                b1f[nt] = __float_as_uint(__ldg(&w1[(koff + k0 + tig + 4) * HD + n]));
            }
            uint32_t a0[4], a1[4], a2[4], a3[4];
            #pragma unroll
            for (int mt = 0; mt < 4; mt++) {
                int r0 = mt * 16 + gid;
                a0[mt] = xu[r0 * HPAD + k0 + tig];
                a1[mt] = xu[(r0 + 8) * HPAD + k0 + tig];
                a2[mt] = xu[r0 * HPAD + k0 + tig + 4];
                a3[mt] = xu[(r0 + 8) * HPAD + k0 + tig + 4];
            }
            #pragma unroll
            for (int mt = 0; mt < 4; mt++)
                #pragma unroll
                for (int nt = 0; nt < 4; nt++)
                    MMA_TF32(c[mt][nt], a0[mt], a1[mt], a2[mt], a3[mt], b0[nt], b1f[nt]);
        }
    }

    #pragma unroll
    for (int nt = 0; nt < 4; nt++) {
        int n = n0 + nt * 8 + 2 * tig;
        float bb0 = __ldg(&b1[n]);
        float bb1 = __ldg(&b1[n + 1]);
        #pragma unroll
        for (int mt = 0; mt < 4; mt++) {
            int m0 = nb + mt * 16 + gid;
            int m1 = m0 + 8;
            *(float2*)&g_A[m0 * HD + n] = make_float2(c[mt][nt][0] + bb0, c[mt][nt][1] + bb1);
            *(float2*)&g_A[m1 * HD + n] = make_float2(c[mt][nt][2] + bb0, c[mt][nt][3] + bb1);
        }
    }
}

// ---------------- chain B2 (side stream): edge hidden + tf32 mma layer-2, bf16 out ----------------
__global__ void __launch_bounds__(128) k_edge(const int* __restrict__ ei,
                                              const float* __restrict__ dist,
                                              const float* __restrict__ conf,
                                              const float* __restrict__ ang,
                                              const float* __restrict__ dep,
                                              const float* __restrict__ w1,
                                              const float* __restrict__ w2,
                                              const float* __restrict__ b2) {
    __shared__ float hid[64 * HPAD];
    int t = threadIdx.x;
    int eb = blockIdx.x * 64;

    float wf0 = w1[(256) * HD + t];
    float wf1 = w1[(257) * HD + t];
    float wf2 = w1[(258) * HD + t];
    float wf3 = w1[(259) * HD + t];
    #pragma unroll 4
    for (int x = 0; x < 64; x++) {
        int e = eb + x;
        int s = ei[e];
        float v = g_A[s * HD + t]
                + dist[e] * wf0 + conf[e] * wf1 + ang[e] * wf2 + dep[e] * wf3;
        hid[x * HPAD + t] = fmaxf(v, 0.0f);
    }
    __syncthreads();

    int warp = t >> 5, lane = t & 31, gid = lane >> 2, tig = lane & 3;
    int n0 = warp * 32;

    float c[4][4][4];
    #pragma unroll
    for (int mt = 0; mt < 4; mt++)
        #pragma unroll
        for (int nt = 0; nt < 4; nt++)
            #pragma unroll
            for (int q = 0; q < 4; q++) c[mt][nt][q] = 0.0f;

    const uint32_t* hidu = (const uint32_t*)hid;

    #pragma unroll 2
    for (int kt = 0; kt < 16; kt++) {
        int k0 = kt * 8;
        uint32_t b0[4], b1[4];
        #pragma unroll
        for (int nt = 0; nt < 4; nt++) {
            int n = n0 + nt * 8 + gid;
            b0[nt] = __float_as_uint(__ldg(&w2[(k0 + tig) * HD + n]));
            b1[nt] = __float_as_uint(__ldg(&w2[(k0 + tig + 4) * HD + n]));
        }
        uint32_t a0[4], a1[4], a2[4], a3[4];
        #pragma unroll
        for (int mt = 0; mt < 4; mt++) {
            int r0 = mt * 16 + gid;
            a0[mt] = hidu[r0 * HPAD + k0 + tig];
            a1[mt] = hidu[(r0 + 8) * HPAD + k0 + tig];
            a2[mt] = hidu[r0 * HPAD + k0 + tig + 4];
            a3[mt] = hidu[(r0 + 8) * HPAD + k0 + tig + 4];
        }
        #pragma unroll
        for (int mt = 0; mt < 4; mt++)
            #pragma unroll
            for (int nt = 0; nt < 4; nt++)
                MMA_TF32(c[mt][nt], a0[mt], a1[mt], a2[mt], a3[mt], b0[nt], b1[nt]);
    }

    // epilogue: + b2, pack bf16x2 -> g_wmh
    #pragma unroll
    for (int nt = 0; nt < 4; nt++) {
        int n = n0 + nt * 8 + 2 * tig;     // even
        float bb0 = __ldg(&b2[n]);
        float bb1 = __ldg(&b2[n + 1]);
        #pragma unroll
        for (int mt = 0; mt < 4; mt++) {
            int e0 = eb + mt * 16 + gid;
            int e1 = e0 + 8;
            __nv_bfloat162 h0 = __float22bfloat162_rn(make_float2(c[mt][nt][0] + bb0, c[mt][nt][1] + bb1));
            __nv_bfloat162 h1 = __float22bfloat162_rn(make_float2(c[mt][nt][2] + bb0, c[mt][nt][3] + bb1));
            g_wmh[e0 * (HD / 2) + (n >> 1)] = *(uint32_t*)&h0;
            g_wmh[e1 * (HD / 2) + (n >> 1)] = *(uint32_t*)&h1;
        }
    }
}

// ---------------- join: aggregation, 2 nodes/block, bf16x2 loads, MLP-8 + cleanup ----------------
__global__ void __launch_bounds__(128) k_agg(const int* __restrict__ ei) {
    int b = blockIdx.x;                 // 0..1023
    int t = threadIdx.x;                // 0..127
    int half = t >> 6;                  // node selector within block
    int tl = t & 63;                    // col-pair index (cols 2tl, 2tl+1)
    int n = b * 2 + half;

    int cnt = g_cnt_dst[n];

    // cleanup: adj for edges [32b, 32b+32)  (k_res done)
    if (t < 32) {
        int e = b * 32 + t;
        g_adj[ei[e] * NN + ei[NE + e]] = 0;
    }
    if (b < 16) g_wcnt_src[b * 128 + t] = 0;

    int base = n * CAP;
    float ax = 0.0f, ay = 0.0f, ws = 0.0f, rs = 0.0f;
    int i = 0;
    for (; i + 8 <= cnt; i += 8) {
        int e[8]; float w[8]; uint32_t v[8];
        #pragma unroll
        for (int j = 0; j < 8; j++) e[j] = g_in_edge[base + i + j];
        #pragma unroll
        for (int j = 0; j < 8; j++) { w[j] = g_wgt[e[j]]; v[j] = __ldg(&g_wmh[e[j] * (HD / 2) + tl]); }
        #pragma unroll
        for (int j = 0; j < 8; j++) {
            float2 f = __bfloat1622float2(*(__nv_bfloat162*)&v[j]);
            ax += f.x * w[j];
            ay += f.y * w[j];
            ws += w[j];
            rs += g_res[e[j]];
        }
    }
    for (; i < cnt; i++) {
        int e = g_in_edge[base + i];
        float w = g_wgt[e];
        uint32_t v = __ldg(&g_wmh[e * (HD / 2) + tl]);
        float2 f = __bfloat1622float2(*(__nv_bfloat162*)&v);
        ax += f.x * w;
        ay += f.y * w;
        ws += w;
        rs += g_res[e];
    }
    float inv = 1.0f / fmaxf(ws, 1e-8f);
    *(float2*)&g_agg[n * HD + 2 * tl] = make_float2(ax * inv, ay * inv);
    if (tl == 0) g_meanr[n] = rs / fmaxf((float)cnt, 1.0f);
}

// ---------------- node MLPs via tf32 mma (64 blocks: 32 tiles x {mu,sigma}) ----------------
__global__ void __launch_bounds__(128) k_node(const float* __restrict__ mu,
                                              const float* __restrict__ muw1, const float* __restrict__ mub1,
                                              const float* __restrict__ muw2, const float* __restrict__ mub2,
                                              const float* __restrict__ sgw1, const float* __restrict__ sgb1,
                                              const float* __restrict__ sgw2, const float* __restrict__ sgb2,
                                              float* __restrict__ out) {
    __shared__ float xs[64 * HPAD];
    __shared__ float mr[64];
    int b = blockIdx.x;
    int path = b & 1;
    int nb = (b >> 1) * 64;
    int t = threadIdx.x;

    if (b < 16) g_cnt_dst[b * 128 + t] = 0;   // safe: k_agg (reader) finished

    for (int x = 0; x < 64; x++) xs[x * HPAD + t] = g_agg[(nb + x) * HD + t];
    if (t < 64) mr[t] = g_meanr[nb + t];
    __syncthreads();

    const float* W1 = path ? sgw1 : muw1;
    const float* B1 = path ? sgb1 : mub1;
    const float* W2 = path ? sgw2 : muw2;
    const float* B2 = path ? sgb2 : mub2;

    int warp = t >> 5, lane = t & 31, gid = lane >> 2, tig = lane & 3;
    int n0 = warp * 32;
    const uint32_t* xu = (const uint32_t*)xs;

    float c[4][4][4];

    #pragma unroll
    for (int mt = 0; mt < 4; mt++)
        #pragma unroll
        for (int nt = 0; nt < 4; nt++)
            #pragma unroll
            for (int q = 0; q < 4; q++) c[mt][nt][q] = 0.0f;

    #pragma unroll 2
    for (int kt = 0; kt < 16; kt++) {
        int k0 = kt * 8;
        uint32_t b0[4], b1[4];
        #pragma unroll
        for (int nt = 0; nt < 4; nt++) {
            int n = n0 + nt * 8 + gid;
            b0[nt] = __float_as_uint(__ldg(&W1[(k0 + tig) * HD + n]));
            b1[nt] = __float_as_uint(__ldg(&W1[(k0 + tig + 4) * HD + n]));
        }
        uint32_t a0[4], a1[4], a2[4], a3[4];
        #pragma unroll
        for (int mt = 0; mt < 4; mt++) {
            int r0 = mt * 16 + gid;
            a0[mt] = xu[r0 * HPAD + k0 + tig];
            a1[mt] = xu[(r0 + 8) * HPAD + k0 + tig];
            a2[mt] = xu[r0 * HPAD + k0 + tig + 4];
            a3[mt] = xu[(r0 + 8) * HPAD + k0 + tig + 4];
        }
        #pragma unroll
        for (int mt = 0; mt < 4; mt++)
            #pragma unroll
            for (int nt = 0; nt < 4; nt++)
                MMA_TF32(c[mt][nt], a0[mt], a1[mt], a2[mt], a3[mt], b0[nt], b1[nt]);
    }
    __syncthreads();

    #pragma unroll
    for (int nt = 0; nt < 4; nt++) {
        int n = n0 + nt * 8 + 2 * tig;
        float bb0 = __ldg(&B1[n]);
        float bb1 = __ldg(&B1[n + 1]);
        float wl0 = 0.0f, wl1 = 0.0f;
        if (path) { wl0 = __ldg(&sgw1[128 * HD + n]); wl1 = __ldg(&sgw1[128 * HD + n + 1]); }
        #pragma unroll
        for (int mt = 0; mt < 4; mt++) {
            int m0 = mt * 16 + gid;
            int m1 = m0 + 8;
            float e0 = path ? mr[m0] : 0.0f;
            float e1 = path ? mr[m1] : 0.0f;
            xs[m0 * HPAD + n]     = fmaxf(c[mt][nt][0] + bb0 + e0 * wl0, 0.0f);
            xs[m0 * HPAD + n + 1] = fmaxf(c[mt][nt][1] + bb1 + e0 * wl1, 0.0f);
            xs[m1 * HPAD + n]     = fmaxf(c[mt][nt][2] + bb0 + e1 * wl0, 0.0f);
            xs[m1 * HPAD + n + 1] = fmaxf(c[mt][nt][3] + bb1 + e1 * wl1, 0.0f);
        }
    }
    __syncthreads();

    #pragma unroll
    for (int mt = 0; mt < 4; mt++)
        #pragma unroll
        for (int nt = 0; nt < 4; nt++)
            #pragma unroll
            for (int q = 0; q < 4; q++) c[mt][nt][q] = 0.0f;

    #pragma unroll 2
    for (int kt = 0; kt < 16; kt++) {
        int k0 = kt * 8;
        uint32_t b0[4], b1[4];
        #pragma unroll
        for (int nt = 0; nt < 4; nt++) {
            int n = n0 + nt * 8 + gid;
            b0[nt] = __float_as_uint(__ldg(&W2[(k0 + tig) * HD + n]));
            b1[nt] = __float_as_uint(__ldg(&W2[(k0 + tig + 4) * HD + n]));
        }
        uint32_t a0[4], a1[4], a2[4], a3[4];
        #pragma unroll
        for (int mt = 0; mt < 4; mt++) {
            int r0 = mt * 16 + gid;
            a0[mt] = xu[r0 * HPAD + k0 + tig];
            a1[mt] = xu[(r0 + 8) * HPAD + k0 + tig];
            a2[mt] = xu[r0 * HPAD + k0 + tig + 4];
            a3[mt] = xu[(r0 + 8) * HPAD + k0 + tig + 4];
        }
        #pragma unroll
        for (int mt = 0; mt < 4; mt++)
            #pragma unroll
            for (int nt = 0; nt < 4; nt++)
                MMA_TF32(c[mt][nt], a0[mt], a1[mt], a2[mt], a3[mt], b0[nt], b1[nt]);
    }

    #pragma unroll
    for (int nt = 0; nt < 4; nt++) {
        int n = n0 + nt * 8 + 2 * tig;
        float bb0 = __ldg(&B2[n]);
        float bb1 = __ldg(&B2[n + 1]);
        #pragma unroll
        for (int mt = 0; mt < 4; mt++) {
            int m0 = nb + mt * 16 + gid;
            int m1 = m0 + 8;
            float v00 = c[mt][nt][0] + bb0, v01 = c[mt][nt][1] + bb1;
            float v10 = c[mt][nt][2] + bb0, v11 = c[mt][nt][3] + bb1;
            if (!path) {
                float2 mu0 = *(const float2*)&mu[m0 * HD + n];
                float2 mu1 = *(const float2*)&mu[m1 * HD + n];
                *(float2*)&out[m0 * HD + n] = make_float2(mu0.x + v00, mu0.y + v01);
                *(float2*)&out[m1 * HD + n] = make_float2(mu1.x + v10, mu1.y + v11);
            } else {
                float s00 = fmaxf(v00, 0.0f) + log1pf(expf(-fabsf(v00)));
                float s01 = fmaxf(v01, 0.0f) + log1pf(expf(-fabsf(v01)));
                float s10 = fmaxf(v10, 0.0f) + log1pf(expf(-fabsf(v10)));
                float s11 = fmaxf(v11, 0.0f) + log1pf(expf(-fabsf(v11)));
                *(float2*)&out[NN * HD + m0 * HD + n] = make_float2(s00, s01);
                *(float2*)&out[NN * HD + m1 * HD + n] = make_float2(s10, s11);
            }
        }
    }
}

// ---------------- launch ----------------
extern "C" void kernel_launch(void* const* d_in, const int* in_sizes, int n_in,
                              void* d_out, int out_size) {
    const float* mu    = (const float*)d_in[0];
    const float* sigma = (const float*)d_in[1];
    const int*   ei    = (const int*)d_in[2];
    const float* dist  = (const float*)d_in[3];
    const float* conf  = (const float*)d_in[4];
    const float* ang   = (const float*)d_in[5];
    const float* dep   = (const float*)d_in[6];
    const float* msgw1 = (const float*)d_in[7];
    const float* msgb1 = (const float*)d_in[8];
    const float* msgw2 = (const float*)d_in[9];
    const float* msgb2 = (const float*)d_in[10];
    const float* muw1  = (const float*)d_in[11];
    const float* mub1  = (const float*)d_in[12];
    const float* muw2  = (const float*)d_in[13];
    const float* mub2  = (const float*)d_in[14];
    const float* sgw1  = (const float*)d_in[15];
    const float* sgb1  = (const float*)d_in[16];
    const float* sgw2  = (const float*)d_in[17];
    const float* sgb2  = (const float*)d_in[18];
    float* out = (float*)d_out;
    float* out_res = out + 2 * NN * HD;

    static cudaStream_t s_side = nullptr;
    static cudaEvent_t  s_fork = nullptr, s_join = nullptr;
    if (s_side == nullptr) {
        cudaStreamCreateWithFlags(&s_side, cudaStreamNonBlocking);
        cudaEventCreateWithFlags(&s_fork, cudaEventDisableTiming);
        cudaEventCreateWithFlags(&s_join, cudaEventDisableTiming);
    }

    // chain B (side stream): nodeA -> edge GEMM
    cudaEventRecord(s_fork, 0);
    cudaStreamWaitEvent(s_side, s_fork, 0);
    k_nodeA<<<NN / 64, 128, 0, s_side>>>(mu, sigma, msgw1, msgb1);
    k_edge<<<NE / 64, 128, 0, s_side>>>(ei, dist, conf, ang, dep, msgw1, msgw2, msgb2);
    cudaEventRecord(s_join, s_side);

    // chain A: adjacency / residuals
    k_scatcnt<<<NE / 256, 256>>>(ei);
    k_fill<<<NE / 256, 256>>>(ei, dist);
    k_res<<<NE / 16, 256>>>(ei, dist, out_res);

    // join, then aggregate + node MLPs
    cudaStreamWaitEvent(0, s_join, 0);
    k_agg<<<NN / 2, 128>>>(ei);
    k_node<<<2 * (NN / 64), 128>>>(mu, muw1, mub1, muw2, mub2, sgw1, sgb1, sgw2, sgb2, out);
}

// round 17
// speedup vs baseline: 1.1074x; 1.0433x over previous
#include <cuda_runtime.h>
#include <cuda_bf16.h>
#include <math.h>
#include <stdint.h>

#define NN 2048
#define NE 32768
#define HD 128
#define CAP 128
#define HPAD 132

// ---------------- scratch (zero at module load; every call restores zeros) ----
__device__ int      g_adj[NN * NN];       // winning (edge+1) per (src,dst), 0 = none
__device__ int      g_wcnt_src[NN];       // unique out-neighbor count
__device__ int      g_cnt_dst[NN];        // in-degree
__device__ int      g_nb_col[NN * CAP];   // src bucket: unique out-neighbor cols (first-touch)
__device__ int      g_in_edge[NN * CAP];  // dst bucket: incoming edge ids
__device__ float    g_A[NN * HD];
__device__ float    g_res[NE];
__device__ float    g_wgt[NE];
__device__ uint32_t g_wmh[NE * (HD / 2)]; // messages as bf16x2
__device__ float    g_agg[NN * HD];
__device__ float    g_meanr[NN];

#define MMA_TF32(c, a0, a1, a2, a3, bb0, bb1)                              \
    asm volatile(                                                          \
        "mma.sync.aligned.m16n8k8.row.col.f32.tf32.tf32.f32 "              \
        "{%0,%1,%2,%3}, {%4,%5,%6,%7}, {%8,%9}, {%0,%1,%2,%3};"            \
        : "+f"((c)[0]), "+f"((c)[1]), "+f"((c)[2]), "+f"((c)[3])           \
        : "r"(a0), "r"(a1), "r"(a2), "r"(a3), "r"(bb0), "r"(bb1))

// ---------------- chain A1: adj scatter + dst bucket + FIRST-TOUCH src bucket ----------------
__global__ void k_scatcnt(const int* __restrict__ ei) {
    int e = blockIdx.x * blockDim.x + threadIdx.x;
    if (e >= NE) return;
    int s = ei[e], d = ei[NE + e];
    int old = atomicMax(&g_adj[s * NN + d], e + 1);
    if (old == 0) {   // exactly one thread per (s,d) sees 0 -> append unique neighbor
        int p = atomicAdd(&g_wcnt_src[s], 1);
        g_nb_col[s * CAP + p] = d;
    }
    int q = atomicAdd(&g_cnt_dst[d], 1);
    g_in_edge[d * CAP + q] = e;
}

// ---------------- chain A2: residuals, 16 lanes per edge (winner dist via adj) ----------------
__global__ void __launch_bounds__(256) k_res(const int* __restrict__ ei,
                                             const float* __restrict__ dist,
                                             float* __restrict__ out_res) {
    int lane = threadIdx.x & 31;
    int l = lane & 15;
    int e = blockIdx.x * 16 + (threadIdx.x >> 5) * 2 + (lane >> 4);
    int s = ei[e], d = ei[NE + e];
    int nw = g_wcnt_src[s];
    int base = s * CAP;
    const int* adj_s = &g_adj[s * NN];
    float sum = 0.0f; int cnt = 0;
    for (int i = l; i < nw; i += 16) {
        int B = g_nb_col[base + i];
        int idxAB = adj_s[B];                 // winner edge+1 for (s,B); >0 by construction
        int idxBC = g_adj[B * NN + d];
        if (idxBC > 0) { sum += dist[idxAB - 1] + dist[idxBC - 1]; cnt++; }
    }
    #pragma unroll
    for (int o = 8; o > 0; o >>= 1) {
        sum += __shfl_down_sync(0xffffffffu, sum, o, 16);
        cnt += __shfl_down_sync(0xffffffffu, cnt, o, 16);
    }
    if (l == 0) {
        float dac = dist[e];
        float mean = (cnt > 0) ? (sum / (float)cnt) : dac;
        float r = fabsf(dac - mean);
        g_res[e] = r;
        g_wgt[e] = expf(-r);
        out_res[e] = r;
    }
}

// ---------------- chain B1 (side stream): nodeA via tf32 mma ----------------
__global__ void __launch_bounds__(128) k_nodeA(const float* __restrict__ mu,
                                               const float* __restrict__ sig,
                                               const float* __restrict__ w1,
                                               const float* __restrict__ b1) {
    __shared__ float xs[64 * HPAD];
    int t = threadIdx.x;
    int nb = blockIdx.x * 64;
    int warp = t >> 5, lane = t & 31, gid = lane >> 2, tig = lane & 3;
    int n0 = warp * 32;
    const uint32_t* xu = (const uint32_t*)xs;

    float c[4][4][4];
    #pragma unroll
    for (int mt = 0; mt < 4; mt++)
        #pragma unroll
        for (int nt = 0; nt < 4; nt++)
            #pragma unroll
            for (int q = 0; q < 4; q++) c[mt][nt][q] = 0.0f;

    #pragma unroll 1
    for (int half = 0; half < 2; half++) {
        const float* src = half ? sig : mu;
        __syncthreads();
        for (int x = 0; x < 64; x++) xs[x * HPAD + t] = src[(nb + x) * HD + t];
        __syncthreads();
        int koff = half * 128;
        #pragma unroll 2
        for (int kt = 0; kt < 16; kt++) {
            int k0 = kt * 8;
            uint32_t b0[4], b1f[4];
            #pragma unroll
            for (int nt = 0; nt < 4; nt++) {
                int n = n0 + nt * 8 + gid;
                b0[nt]  = __float_as_uint(__ldg(&w1[(koff + k0 + tig) * HD + n]));
                b1f[nt] = __float_as_uint(__ldg(&w1[(koff + k0 + tig + 4) * HD + n]));
            }
            uint32_t a0[4], a1[4], a2[4], a3[4];
            #pragma unroll
            for (int mt = 0; mt < 4; mt++) {
                int r0 = mt * 16 + gid;
                a0[mt] = xu[r0 * HPAD + k0 + tig];
                a1[mt] = xu[(r0 + 8) * HPAD + k0 + tig];
                a2[mt] = xu[r0 * HPAD + k0 + tig + 4];
                a3[mt] = xu[(r0 + 8) * HPAD + k0 + tig + 4];
            }
            #pragma unroll
            for (int mt = 0; mt < 4; mt++)
                #pragma unroll
                for (int nt = 0; nt < 4; nt++)
                    MMA_TF32(c[mt][nt], a0[mt], a1[mt], a2[mt], a3[mt], b0[nt], b1f[nt]);
        }
    }

    #pragma unroll
    for (int nt = 0; nt < 4; nt++) {
        int n = n0 + nt * 8 + 2 * tig;
        float bb0 = __ldg(&b1[n]);
        float bb1 = __ldg(&b1[n + 1]);
        #pragma unroll
        for (int mt = 0; mt < 4; mt++) {
            int m0 = nb + mt * 16 + gid;
            int m1 = m0 + 8;
            *(float2*)&g_A[m0 * HD + n] = make_float2(c[mt][nt][0] + bb0, c[mt][nt][1] + bb1);
            *(float2*)&g_A[m1 * HD + n] = make_float2(c[mt][nt][2] + bb0, c[mt][nt][3] + bb1);
        }
    }
}

// ---------------- chain B2 (side stream): edge hidden + tf32 mma layer-2, bf16 out ----------------
__global__ void __launch_bounds__(128) k_edge(const int* __restrict__ ei,
                                              const float* __restrict__ dist,
                                              const float* __restrict__ conf,
                                              const float* __restrict__ ang,
                                              const float* __restrict__ dep,
                                              const float* __restrict__ w1,
                                              const float* __restrict__ w2,
                                              const float* __restrict__ b2) {
    __shared__ float hid[64 * HPAD];
    int t = threadIdx.x;
    int eb = blockIdx.x * 64;

    float wf0 = w1[(256) * HD + t];
    float wf1 = w1[(257) * HD + t];
    float wf2 = w1[(258) * HD + t];
    float wf3 = w1[(259) * HD + t];
    #pragma unroll 4
    for (int x = 0; x < 64; x++) {
        int e = eb + x;
        int s = ei[e];
        float v = g_A[s * HD + t]
                + dist[e] * wf0 + conf[e] * wf1 + ang[e] * wf2 + dep[e] * wf3;
        hid[x * HPAD + t] = fmaxf(v, 0.0f);
    }
    __syncthreads();

    int warp = t >> 5, lane = t & 31, gid = lane >> 2, tig = lane & 3;
    int n0 = warp * 32;

    float c[4][4][4];
    #pragma unroll
    for (int mt = 0; mt < 4; mt++)
        #pragma unroll
        for (int nt = 0; nt < 4; nt++)
            #pragma unroll
            for (int q = 0; q < 4; q++) c[mt][nt][q] = 0.0f;

    const uint32_t* hidu = (const uint32_t*)hid;

    #pragma unroll 2
    for (int kt = 0; kt < 16; kt++) {
        int k0 = kt * 8;
        uint32_t b0[4], b1[4];
        #pragma unroll
        for (int nt = 0; nt < 4; nt++) {
            int n = n0 + nt * 8 + gid;
            b0[nt] = __float_as_uint(__ldg(&w2[(k0 + tig) * HD + n]));
            b1[nt] = __float_as_uint(__ldg(&w2[(k0 + tig + 4) * HD + n]));
        }
        uint32_t a0[4], a1[4], a2[4], a3[4];
        #pragma unroll
        for (int mt = 0; mt < 4; mt++) {
            int r0 = mt * 16 + gid;
            a0[mt] = hidu[r0 * HPAD + k0 + tig];
            a1[mt] = hidu[(r0 + 8) * HPAD + k0 + tig];
            a2[mt] = hidu[r0 * HPAD + k0 + tig + 4];
            a3[mt] = hidu[(r0 + 8) * HPAD + k0 + tig + 4];
        }
        #pragma unroll
        for (int mt = 0; mt < 4; mt++)
            #pragma unroll
            for (int nt = 0; nt < 4; nt++)
                MMA_TF32(c[mt][nt], a0[mt], a1[mt], a2[mt], a3[mt], b0[nt], b1[nt]);
    }

    #pragma unroll
    for (int nt = 0; nt < 4; nt++) {
        int n = n0 + nt * 8 + 2 * tig;     // even
        float bb0 = __ldg(&b2[n]);
        float bb1 = __ldg(&b2[n + 1]);
        #pragma unroll
        for (int mt = 0; mt < 4; mt++) {
            int e0 = eb + mt * 16 + gid;
            int e1 = e0 + 8;
            __nv_bfloat162 h0 = __float22bfloat162_rn(make_float2(c[mt][nt][0] + bb0, c[mt][nt][1] + bb1));
            __nv_bfloat162 h1 = __float22bfloat162_rn(make_float2(c[mt][nt][2] + bb0, c[mt][nt][3] + bb1));
            g_wmh[e0 * (HD / 2) + (n >> 1)] = *(uint32_t*)&h0;
            g_wmh[e1 * (HD / 2) + (n >> 1)] = *(uint32_t*)&h1;
        }
    }
}

// ---------------- join: aggregation (2 nodes/block, bf16x2, MLP-8) + cleanup ----------------
__global__ void __launch_bounds__(128) k_agg(const int* __restrict__ ei) {
    int b = blockIdx.x;                 // 0..1023
    int t = threadIdx.x;
    int half = t >> 6;
    int tl = t & 63;
    int n = b * 2 + half;

    int cnt = g_cnt_dst[n];

    if (t < 32) {
        int e = b * 32 + t;
        g_adj[ei[e] * NN + ei[NE + e]] = 0;
    }
    if (b < 16) g_wcnt_src[b * 128 + t] = 0;

    int base = n * CAP;
    float ax = 0.0f, ay = 0.0f, ws = 0.0f, rs = 0.0f;
    int i = 0;
    for (; i + 8 <= cnt; i += 8) {
        int e[8]; float w[8]; uint32_t v[8];
        #pragma unroll
        for (int j = 0; j < 8; j++) e[j] = g_in_edge[base + i + j];
        #pragma unroll
        for (int j = 0; j < 8; j++) { w[j] = g_wgt[e[j]]; v[j] = __ldg(&g_wmh[e[j] * (HD / 2) + tl]); }
        #pragma unroll
        for (int j = 0; j < 8; j++) {
            float2 f = __bfloat1622float2(*(__nv_bfloat162*)&v[j]);
            ax += f.x * w[j];
            ay += f.y * w[j];
            ws += w[j];
            rs += g_res[e[j]];
        }
    }
    for (; i < cnt; i++) {
        int e = g_in_edge[base + i];
        float w = g_wgt[e];
        uint32_t v = __ldg(&g_wmh[e * (HD / 2) + tl]);
        float2 f = __bfloat1622float2(*(__nv_bfloat162*)&v);
        ax += f.x * w;
        ay += f.y * w;
        ws += w;
        rs += g_res[e];
    }
    float inv = 1.0f / fmaxf(ws, 1e-8f);
    *(float2*)&g_agg[n * HD + 2 * tl] = make_float2(ax * inv, ay * inv);
    if (tl == 0) g_meanr[n] = rs / fmaxf((float)cnt, 1.0f);
}

// ---------------- node MLPs via tf32 mma (64 blocks: 32 tiles x {mu,sigma}) ----------------
__global__ void __launch_bounds__(128) k_node(const float* __restrict__ mu,
                                              const float* __restrict__ muw1, const float* __restrict__ mub1,
                                              const float* __restrict__ muw2, const float* __restrict__ mub2,
                                              const float* __restrict__ sgw1, const float* __restrict__ sgb1,
                                              const float* __restrict__ sgw2, const float* __restrict__ sgb2,
                                              float* __restrict__ out) {
    __shared__ float xs[64 * HPAD];
    __shared__ float mr[64];
    int b = blockIdx.x;
    int path = b & 1;
    int nb = (b >> 1) * 64;
    int t = threadIdx.x;

    if (b < 16) g_cnt_dst[b * 128 + t] = 0;   // safe: k_agg (reader) finished

    for (int x = 0; x < 64; x++) xs[x * HPAD + t] = g_agg[(nb + x) * HD + t];
    if (t < 64) mr[t] = g_meanr[nb + t];
    __syncthreads();

    const float* W1 = path ? sgw1 : muw1;
    const float* B1 = path ? sgb1 : mub1;
    const float* W2 = path ? sgw2 : muw2;
    const float* B2 = path ? sgb2 : mub2;

    int warp = t >> 5, lane = t & 31, gid = lane >> 2, tig = lane & 3;
    int n0 = warp * 32;
    const uint32_t* xu = (const uint32_t*)xs;

    float c[4][4][4];

    #pragma unroll
    for (int mt = 0; mt < 4; mt++)
        #pragma unroll
        for (int nt = 0; nt < 4; nt++)
            #pragma unroll
            for (int q = 0; q < 4; q++) c[mt][nt][q] = 0.0f;

    #pragma unroll 2
    for (int kt = 0; kt < 16; kt++) {
        int k0 = kt * 8;
        uint32_t b0[4], b1[4];
        #pragma unroll
        for (int nt = 0; nt < 4; nt++) {
            int n = n0 + nt * 8 + gid;
            b0[nt] = __float_as_uint(__ldg(&W1[(k0 + tig) * HD + n]));
            b1[nt] = __float_as_uint(__ldg(&W1[(k0 + tig + 4) * HD + n]));
        }
        uint32_t a0[4], a1[4], a2[4], a3[4];
        #pragma unroll
        for (int mt = 0; mt < 4; mt++) {
            int r0 = mt * 16 + gid;
            a0[mt] = xu[r0 * HPAD + k0 + tig];
            a1[mt] = xu[(r0 + 8) * HPAD + k0 + tig];
            a2[mt] = xu[r0 * HPAD + k0 + tig + 4];
            a3[mt] = xu[(r0 + 8) * HPAD + k0 + tig + 4];
        }
        #pragma unroll
        for (int mt = 0; mt < 4; mt++)
            #pragma unroll
            for (int nt = 0; nt < 4; nt++)
                MMA_TF32(c[mt][nt], a0[mt], a1[mt], a2[mt], a3[mt], b0[nt], b1[nt]);
    }
    __syncthreads();

    #pragma unroll
    for (int nt = 0; nt < 4; nt++) {
        int n = n0 + nt * 8 + 2 * tig;
        float bb0 = __ldg(&B1[n]);
        float bb1 = __ldg(&B1[n + 1]);
        float wl0 = 0.0f, wl1 = 0.0f;
        if (path) { wl0 = __ldg(&sgw1[128 * HD + n]); wl1 = __ldg(&sgw1[128 * HD + n + 1]); }
        #pragma unroll
        for (int mt = 0; mt < 4; mt++) {
            int m0 = mt * 16 + gid;
            int m1 = m0 + 8;
            float e0 = path ? mr[m0] : 0.0f;
            float e1 = path ? mr[m1] : 0.0f;
            xs[m0 * HPAD + n]     = fmaxf(c[mt][nt][0] + bb0 + e0 * wl0, 0.0f);
            xs[m0 * HPAD + n + 1] = fmaxf(c[mt][nt][1] + bb1 + e0 * wl1, 0.0f);
            xs[m1 * HPAD + n]     = fmaxf(c[mt][nt][2] + bb0 + e1 * wl0, 0.0f);
            xs[m1 * HPAD + n + 1] = fmaxf(c[mt][nt][3] + bb1 + e1 * wl1, 0.0f);
        }
    }
    __syncthreads();

    #pragma unroll
    for (int mt = 0; mt < 4; mt++)
        #pragma unroll
        for (int nt = 0; nt < 4; nt++)
            #pragma unroll
            for (int q = 0; q < 4; q++) c[mt][nt][q] = 0.0f;

    #pragma unroll 2
    for (int kt = 0; kt < 16; kt++) {
        int k0 = kt * 8;
        uint32_t b0[4], b1[4];
        #pragma unroll
        for (int nt = 0; nt < 4; nt++) {
            int n = n0 + nt * 8 + gid;
            b0[nt] = __float_as_uint(__ldg(&W2[(k0 + tig) * HD + n]));
            b1[nt] = __float_as_uint(__ldg(&W2[(k0 + tig + 4) * HD + n]));
        }
        uint32_t a0[4], a1[4], a2[4], a3[4];
        #pragma unroll
        for (int mt = 0; mt < 4; mt++) {
            int r0 = mt * 16 + gid;
            a0[mt] = xu[r0 * HPAD + k0 + tig];
            a1[mt] = xu[(r0 + 8) * HPAD + k0 + tig];
            a2[mt] = xu[r0 * HPAD + k0 + tig + 4];
            a3[mt] = xu[(r0 + 8) * HPAD + k0 + tig + 4];
        }
        #pragma unroll
        for (int mt = 0; mt < 4; mt++)
            #pragma unroll
            for (int nt = 0; nt < 4; nt++)
                MMA_TF32(c[mt][nt], a0[mt], a1[mt], a2[mt], a3[mt], b0[nt], b1[nt]);
    }

    #pragma unroll
    for (int nt = 0; nt < 4; nt++) {
        int n = n0 + nt * 8 + 2 * tig;
        float bb0 = __ldg(&B2[n]);
        float bb1 = __ldg(&B2[n + 1]);
        #pragma unroll
        for (int mt = 0; mt < 4; mt++) {
            int m0 = nb + mt * 16 + gid;
            int m1 = m0 + 8;
            float v00 = c[mt][nt][0] + bb0, v01 = c[mt][nt][1] + bb1;
            float v10 = c[mt][nt][2] + bb0, v11 = c[mt][nt][3] + bb1;
            if (!path) {
                float2 mu0 = *(const float2*)&mu[m0 * HD + n];
                float2 mu1 = *(const float2*)&mu[m1 * HD + n];
                *(float2*)&out[m0 * HD + n] = make_float2(mu0.x + v00, mu0.y + v01);
                *(float2*)&out[m1 * HD + n] = make_float2(mu1.x + v10, mu1.y + v11);
            } else {
                float s00 = fmaxf(v00, 0.0f) + log1pf(expf(-fabsf(v00)));
                float s01 = fmaxf(v01, 0.0f) + log1pf(expf(-fabsf(v01)));
                float s10 = fmaxf(v10, 0.0f) + log1pf(expf(-fabsf(v10)));
                float s11 = fmaxf(v11, 0.0f) + log1pf(expf(-fabsf(v11)));
                *(float2*)&out[NN * HD + m0 * HD + n] = make_float2(s00, s01);
                *(float2*)&out[NN * HD + m1 * HD + n] = make_float2(s10, s11);
            }
        }
    }
}

// ---------------- launch ----------------
extern "C" void kernel_launch(void* const* d_in, const int* in_sizes, int n_in,
                              void* d_out, int out_size) {
    const float* mu    = (const float*)d_in[0];
    const float* sigma = (const float*)d_in[1];
    const int*   ei    = (const int*)d_in[2];
    const float* dist  = (const float*)d_in[3];
    const float* conf  = (const float*)d_in[4];
    const float* ang   = (const float*)d_in[5];
    const float* dep   = (const float*)d_in[6];
    const float* msgw1 = (const float*)d_in[7];
    const float* msgb1 = (const float*)d_in[8];
    const float* msgw2 = (const float*)d_in[9];
    const float* msgb2 = (const float*)d_in[10];
    const float* muw1  = (const float*)d_in[11];
    const float* mub1  = (const float*)d_in[12];
    const float* muw2  = (const float*)d_in[13];
    const float* mub2  = (const float*)d_in[14];
    const float* sgw1  = (const float*)d_in[15];
    const float* sgb1  = (const float*)d_in[16];
    const float* sgw2  = (const float*)d_in[17];
    const float* sgb2  = (const float*)d_in[18];
    float* out = (float*)d_out;
    float* out_res = out + 2 * NN * HD;

    static cudaStream_t s_side = nullptr;
    static cudaEvent_t  s_fork = nullptr, s_join = nullptr;
    if (s_side == nullptr) {
        cudaStreamCreateWithFlags(&s_side, cudaStreamNonBlocking);
        cudaEventCreateWithFlags(&s_fork, cudaEventDisableTiming);
        cudaEventCreateWithFlags(&s_join, cudaEventDisableTiming);
    }

    // chain B (side stream): nodeA -> edge GEMM
    cudaEventRecord(s_fork, 0);
    cudaStreamWaitEvent(s_side, s_fork, 0);
    k_nodeA<<<NN / 64, 128, 0, s_side>>>(mu, sigma, msgw1, msgb1);
    k_edge<<<NE / 64, 128, 0, s_side>>>(ei, dist, conf, ang, dep, msgw1, msgw2, msgb2);
    cudaEventRecord(s_join, s_side);

    // chain A: adjacency / residuals (fill eliminated via first-touch append)
    k_scatcnt<<<NE / 256, 256>>>(ei);
    k_res<<<NE / 16, 256>>>(ei, dist, out_res);

    // join, then aggregate + node MLPs
    cudaStreamWaitEvent(0, s_join, 0);
    k_agg<<<NN / 2, 128>>>(ei);
    k_node<<<2 * (NN / 64), 128>>>(mu, muw1, mub1, muw2, mub2, sgw1, sgb1, sgw2, sgb2, out);
}